// round 10
// baseline (speedup 1.0000x reference)
#include <cuda_runtime.h>
#include <cstdint>

// ---------------------------------------------------------------------------
// SpecAugment on GB300 — FINAL (R5 configuration, best measured: 74.2us).
//  * Single fused kernel, one graph node.
//  * Subkeys of jax.random.split(key(42),3) baked in at compile time
//    (constexpr threefry2x32, JAX partitionable path) — bit-exact masks,
//    rel_err = 0.0.
//  * Warp 0 computes the 8 runtime threefry hashes (SIMT over lanes 0..7)
//    + mask intervals once per block; smem broadcast.
//  * 256-thread block, 4 float4/thread (MLP_p1=4), grid (T/32, B):
//    occ ~82%, regs ~32 — the measured sweet spot of this session.
//  * Streaming __ldcs/__stcs; loads predicated off where the output is
//    provably zero (time-masked rows, fully freq-masked lanes) ->
//    422 MB total traffic = analytic floor at ~6.2 TB/s achieved.
// B=128, T=4000, F=128.
// ---------------------------------------------------------------------------

#define FREQ_MASK_SIZE 27.0f
#define TIME_MASK_PCT  0.25f

// ---- constexpr Threefry2x32 (20 rounds) for compile-time subkeys ----------
struct TFPair { unsigned a, b; };

constexpr unsigned rotl32c(unsigned x, int r) {
    return (x << r) | (x >> (32 - r));
}

constexpr TFPair threefry_const(unsigned k0, unsigned k1,
                                unsigned x0, unsigned x1) {
    unsigned ks2 = k0 ^ k1 ^ 0x1BD11BDAu;
    x0 += k0; x1 += k1;
    const int R[8] = {13, 15, 26, 6, 17, 29, 16, 24};
    for (int g = 0; g < 5; g++) {
        const int* r = (g % 2 == 0) ? R : R + 4;
        for (int i = 0; i < 4; i++) {
            x0 += x1; x1 = rotl32c(x1, r[i]); x1 ^= x0;
        }
        switch (g) {
            case 0: x0 += k1;  x1 += ks2 + 1u; break;
            case 1: x0 += ks2; x1 += k0 + 2u;  break;
            case 2: x0 += k0;  x1 += k1 + 3u;  break;
            case 3: x0 += k1;  x1 += ks2 + 4u; break;
            case 4: x0 += ks2; x1 += k0 + 5u;  break;
        }
    }
    return TFPair{x0, x1};
}

// split(key(42), 3), partitionable path: child i = threefry(key, (0, i))
constexpr TFPair KF = threefry_const(0u, 42u, 0u, 0u);
constexpr TFPair KV = threefry_const(0u, 42u, 0u, 1u);
constexpr TFPair KS = threefry_const(0u, 42u, 0u, 2u);

// ---- device Threefry2x32 (same schedule) ----------------------------------
__device__ __forceinline__ uint2 threefry2x32(unsigned k0, unsigned k1,
                                              unsigned x0, unsigned x1) {
    unsigned ks2 = k0 ^ k1 ^ 0x1BD11BDAu;
    x0 += k0; x1 += k1;
#define TF_RND(r) { x0 += x1; x1 = __funnelshift_l(x1, x1, (r)); x1 ^= x0; }
    TF_RND(13) TF_RND(15) TF_RND(26) TF_RND(6)
    x0 += k1;  x1 += ks2 + 1u;
    TF_RND(17) TF_RND(29) TF_RND(16) TF_RND(24)
    x0 += ks2; x1 += k0 + 2u;
    TF_RND(13) TF_RND(15) TF_RND(26) TF_RND(6)
    x0 += k0;  x1 += k1 + 3u;
    TF_RND(17) TF_RND(29) TF_RND(16) TF_RND(24)
    x0 += k1;  x1 += ks2 + 4u;
    TF_RND(13) TF_RND(15) TF_RND(26) TF_RND(6)
    x0 += ks2; x1 += k0 + 5u;
#undef TF_RND
    return make_uint2(x0, x1);
}

__device__ __forceinline__ float bits_to_unit(unsigned bits) {
    return __uint_as_float((bits >> 9) | 0x3F800000u) - 1.0f;
}

// ---------------------------------------------------------------------------
// Fused kernel. Block = 256 threads = 8 warps; warp w handles t-rows
// [blockIdx.x*32 + w*4, +4) with 32 float4 lanes over F=128. Grid=(T/32, B).
// ---------------------------------------------------------------------------
__global__ void __launch_bounds__(256)
specaug_fused_kernel(const float4* __restrict__ x,
                     float4* __restrict__ out,
                     const int* __restrict__ x_len,
                     int T) {
    __shared__ int s_m[8];   // fs0, fe0, fs1, fe1, ts0, te0, ts1, te1

    const int b = blockIdx.y;
    const int w = threadIdx.x >> 5;
    const int q = threadIdx.x & 31;

    // ---- warp 0: hashes + mask intervals, once per block -------------------
    if (w == 0) {
        const unsigned sel = (unsigned)q & 7u;
        unsigned k0, k1, j;
        if (sel < 4u)      { k0 = KF.a; k1 = KF.b; j = sel; }
        else if (sel < 6u) { k0 = KV.a; k1 = KV.b; j = 2u * (unsigned)b + (sel - 4u); }
        else               { k0 = KS.a; k1 = KS.b; j = 2u * (unsigned)b + (sel - 6u); }
        uint2 h = threefry2x32(k0, k1, 0u, j);
        float u = bits_to_unit(h.x ^ h.y);

        const unsigned FULL = 0xFFFFFFFFu;
        float u00 = __shfl_sync(FULL, u, 0);
        float u01 = __shfl_sync(FULL, u, 1);
        float u10 = __shfl_sync(FULL, u, 2);
        float u11 = __shfl_sync(FULL, u, 3);
        float uv0 = __shfl_sync(FULL, u, 4);
        float uv1 = __shfl_sync(FULL, u, 5);
        float us0 = __shfl_sync(FULL, u, 6);
        float us1 = __shfl_sync(FULL, u, 7);

        if (q == 0) {
            // frequency masks (fp32 ops matching the reference exactly);
            // floor results are exact small integers -> store as int.
            const float Ff = 128.0f;
            float fv0 = __fmul_rn(u00, FREQ_MASK_SIZE);
            float fb0 = __fmul_rn(u01, __fsub_rn(Ff, fv0));
            s_m[0] = (int)floorf(fb0);
            s_m[1] = (int)floorf(__fadd_rn(fb0, fv0));
            float fv1 = __fmul_rn(u10, FREQ_MASK_SIZE);
            float fb1 = __fmul_rn(u11, __fsub_rn(Ff, fv1));
            s_m[2] = (int)floorf(fb1);
            s_m[3] = (int)floorf(__fadd_rn(fb1, fv1));

            // adaptive time masks for batch b
            float xl = (float)__ldg(x_len + b);
            float tparam = floorf(__fmul_rn(TIME_MASK_PCT, xl));

            float tv0 = __fmul_rn(uv0, tparam);
            float tb0 = __fmul_rn(us0, __fsub_rn(xl, tv0));
            s_m[4] = (int)floorf(tb0);
            s_m[5] = (int)floorf(__fadd_rn(tb0, tv0));
            float tv1 = __fmul_rn(uv1, tparam);
            float tb1 = __fmul_rn(us1, __fsub_rn(xl, tv1));
            s_m[6] = (int)floorf(tb1);
            s_m[7] = (int)floorf(__fadd_rn(tb1, tv1));
        }
    }
    __syncthreads();

    const int fs0 = s_m[0], fe0 = s_m[1], fs1 = s_m[2], fe1 = s_m[3];
    const int ts0 = s_m[4], te0 = s_m[5], ts1 = s_m[6], te1 = s_m[7];

    // ---- per-lane frequency multiplier for bins 4q..4q+3 -------------------
    float4 fm;
    {
        const int f0 = 4 * q;
        const int f1 = f0 + 1, f2 = f0 + 2, f3 = f0 + 3;
        fm.x = ((f0 >= fs0 && f0 < fe0) || (f0 >= fs1 && f0 < fe1)) ? 0.f : 1.f;
        fm.y = ((f1 >= fs0 && f1 < fe0) || (f1 >= fs1 && f1 < fe1)) ? 0.f : 1.f;
        fm.z = ((f2 >= fs0 && f2 < fe0) || (f2 >= fs1 && f2 < fe1)) ? 0.f : 1.f;
        fm.w = ((f3 >= fs0 && f3 < fe0) || (f3 >= fs1 && f3 < fe1)) ? 0.f : 1.f;
    }
    const bool fmzero = (fm.x + fm.y + fm.z + fm.w) == 0.f;

    // ---- streaming apply: 4 rows per thread --------------------------------
    const int t0 = blockIdx.x * 32 + w * 4;
    const size_t base = ((size_t)b * T + t0) * 32 + q;

    bool p[4];
    #pragma unroll
    for (int i = 0; i < 4; i++) {
        const int t = t0 + i;
        const bool tmask = (t >= ts0 && t < te0) || (t >= ts1 && t < te1);
        p[i] = !(tmask || fmzero);
    }

    float4 v[4];
    #pragma unroll
    for (int i = 0; i < 4; i++) {
        v[i] = make_float4(0.f, 0.f, 0.f, 0.f);
        if (p[i]) v[i] = __ldcs(x + base + (size_t)i * 32);
    }

    #pragma unroll
    for (int i = 0; i < 4; i++) {
        float4 r;
        if (p[i]) {
            r.x = v[i].x * fm.x;
            r.y = v[i].y * fm.y;
            r.z = v[i].z * fm.z;
            r.w = v[i].w * fm.w;
        } else {
            r = make_float4(0.f, 0.f, 0.f, 0.f);
        }
        __stcs(out + base + (size_t)i * 32, r);
    }
}

extern "C" void kernel_launch(void* const* d_in, const int* in_sizes, int n_in,
                              void* d_out, int out_size) {
    const float* x     = (const float*)d_in[0];
    const int*   x_len = (const int*)d_in[1];
    float*       out   = (float*)d_out;

    const int B = in_sizes[1];                 // 128
    const int F = 128;                         // fixed by problem shape
    const int T = in_sizes[0] / (B * F);       // 4000

    dim3 grid(T / 32, B);                      // 125 x 128 blocks, one node
    specaug_fused_kernel<<<grid, 256>>>(
        (const float4*)x, (float4*)out, x_len, T);
    (void)n_in; (void)out_size; (void)F;
}

// round 11
// speedup vs baseline: 1.0181x; 1.0181x over previous
#include <cuda_runtime.h>
#include <cstdint>

// ---------------------------------------------------------------------------
// SpecAugment on GB300 — R11: R5 streaming body + warp-0-materialized masks.
//  * Warp 0: 8 threefry hashes (SIMT lanes 0..7) -> intervals -> per-lane
//    fm table (smem float4[32]), block row-mask bitmap, fmzero lane bitmap.
//  * Other warps: 1x LDS.128 + bit tests instead of ~28 ALU ops each.
//  * 256-thread block, 4 float4/thread, grid (T/32, B); streaming ld/st,
//    loads predicated off where output is provably zero.
// B=128, T=4000, F=128.
// ---------------------------------------------------------------------------

#define FREQ_MASK_SIZE 27.0f
#define TIME_MASK_PCT  0.25f

// ---- constexpr Threefry2x32 (20 rounds) for compile-time subkeys ----------
struct TFPair { unsigned a, b; };

constexpr unsigned rotl32c(unsigned x, int r) {
    return (x << r) | (x >> (32 - r));
}

constexpr TFPair threefry_const(unsigned k0, unsigned k1,
                                unsigned x0, unsigned x1) {
    unsigned ks2 = k0 ^ k1 ^ 0x1BD11BDAu;
    x0 += k0; x1 += k1;
    const int R[8] = {13, 15, 26, 6, 17, 29, 16, 24};
    for (int g = 0; g < 5; g++) {
        const int* r = (g % 2 == 0) ? R : R + 4;
        for (int i = 0; i < 4; i++) {
            x0 += x1; x1 = rotl32c(x1, r[i]); x1 ^= x0;
        }
        switch (g) {
            case 0: x0 += k1;  x1 += ks2 + 1u; break;
            case 1: x0 += ks2; x1 += k0 + 2u;  break;
            case 2: x0 += k0;  x1 += k1 + 3u;  break;
            case 3: x0 += k1;  x1 += ks2 + 4u; break;
            case 4: x0 += ks2; x1 += k0 + 5u;  break;
        }
    }
    return TFPair{x0, x1};
}

// split(key(42), 3), partitionable path: child i = threefry(key, (0, i))
constexpr TFPair KF = threefry_const(0u, 42u, 0u, 0u);
constexpr TFPair KV = threefry_const(0u, 42u, 0u, 1u);
constexpr TFPair KS = threefry_const(0u, 42u, 0u, 2u);

// ---- device Threefry2x32 (same schedule) ----------------------------------
__device__ __forceinline__ uint2 threefry2x32(unsigned k0, unsigned k1,
                                              unsigned x0, unsigned x1) {
    unsigned ks2 = k0 ^ k1 ^ 0x1BD11BDAu;
    x0 += k0; x1 += k1;
#define TF_RND(r) { x0 += x1; x1 = __funnelshift_l(x1, x1, (r)); x1 ^= x0; }
    TF_RND(13) TF_RND(15) TF_RND(26) TF_RND(6)
    x0 += k1;  x1 += ks2 + 1u;
    TF_RND(17) TF_RND(29) TF_RND(16) TF_RND(24)
    x0 += ks2; x1 += k0 + 2u;
    TF_RND(13) TF_RND(15) TF_RND(26) TF_RND(6)
    x0 += k0;  x1 += k1 + 3u;
    TF_RND(17) TF_RND(29) TF_RND(16) TF_RND(24)
    x0 += k1;  x1 += ks2 + 4u;
    TF_RND(13) TF_RND(15) TF_RND(26) TF_RND(6)
    x0 += ks2; x1 += k0 + 5u;
#undef TF_RND
    return make_uint2(x0, x1);
}

__device__ __forceinline__ float bits_to_unit(unsigned bits) {
    return __uint_as_float((bits >> 9) | 0x3F800000u) - 1.0f;
}

// ---------------------------------------------------------------------------
// Fused kernel. Block = 256 threads = 8 warps; warp w handles t-rows
// [blockIdx.x*32 + w*4, +4) with 32 float4 lanes over F=128. Grid=(T/32, B).
// ---------------------------------------------------------------------------
__global__ void __launch_bounds__(256)
specaug_fused_kernel(const float4* __restrict__ x,
                     float4* __restrict__ out,
                     const int* __restrict__ x_len,
                     int T) {
    __shared__ int      s_iv[8];    // fs0,fe0,fs1,fe1, ts0,te0,ts1,te1
    __shared__ float4   s_fm[32];   // per-lane freq multiplier (bins 4q..4q+3)
    __shared__ unsigned s_tbits;    // bit r = time-mask for block row r (0..31)
    __shared__ unsigned s_fmz;      // bit q = all 4 bins of lane q masked

    const int b = blockIdx.y;
    const int w = threadIdx.x >> 5;
    const int q = threadIdx.x & 31;

    // ---- warp 0: hashes -> intervals -> materialized mask tables -----------
    if (w == 0) {
        const unsigned sel = (unsigned)q & 7u;
        unsigned k0, k1, j;
        if (sel < 4u)      { k0 = KF.a; k1 = KF.b; j = sel; }
        else if (sel < 6u) { k0 = KV.a; k1 = KV.b; j = 2u * (unsigned)b + (sel - 4u); }
        else               { k0 = KS.a; k1 = KS.b; j = 2u * (unsigned)b + (sel - 6u); }
        uint2 h = threefry2x32(k0, k1, 0u, j);
        float u = bits_to_unit(h.x ^ h.y);

        const unsigned FULL = 0xFFFFFFFFu;
        float u00 = __shfl_sync(FULL, u, 0);
        float u01 = __shfl_sync(FULL, u, 1);
        float u10 = __shfl_sync(FULL, u, 2);
        float u11 = __shfl_sync(FULL, u, 3);
        float uv0 = __shfl_sync(FULL, u, 4);
        float uv1 = __shfl_sync(FULL, u, 5);
        float us0 = __shfl_sync(FULL, u, 6);
        float us1 = __shfl_sync(FULL, u, 7);

        if (q == 0) {
            // frequency masks (fp32 ops matching the reference exactly);
            // floor results are exact small integers -> store as int.
            const float Ff = 128.0f;
            float fv0 = __fmul_rn(u00, FREQ_MASK_SIZE);
            float fb0 = __fmul_rn(u01, __fsub_rn(Ff, fv0));
            s_iv[0] = (int)floorf(fb0);
            s_iv[1] = (int)floorf(__fadd_rn(fb0, fv0));
            float fv1 = __fmul_rn(u10, FREQ_MASK_SIZE);
            float fb1 = __fmul_rn(u11, __fsub_rn(Ff, fv1));
            s_iv[2] = (int)floorf(fb1);
            s_iv[3] = (int)floorf(__fadd_rn(fb1, fv1));

            // adaptive time masks for batch b
            float xl = (float)__ldg(x_len + b);
            float tparam = floorf(__fmul_rn(TIME_MASK_PCT, xl));

            float tv0 = __fmul_rn(uv0, tparam);
            float tb0 = __fmul_rn(us0, __fsub_rn(xl, tv0));
            s_iv[4] = (int)floorf(tb0);
            s_iv[5] = (int)floorf(__fadd_rn(tb0, tv0));
            float tv1 = __fmul_rn(uv1, tparam);
            float tb1 = __fmul_rn(us1, __fsub_rn(xl, tv1));
            s_iv[6] = (int)floorf(tb1);
            s_iv[7] = (int)floorf(__fadd_rn(tb1, tv1));
        }
        __syncwarp();

        const int fs0 = s_iv[0], fe0 = s_iv[1], fs1 = s_iv[2], fe1 = s_iv[3];
        const int ts0 = s_iv[4], te0 = s_iv[5], ts1 = s_iv[6], te1 = s_iv[7];

        // per-lane freq multiplier table
        const int f0 = 4 * q;
        const int f1 = f0 + 1, f2 = f0 + 2, f3 = f0 + 3;
        const bool m0 = (f0 >= fs0 && f0 < fe0) || (f0 >= fs1 && f0 < fe1);
        const bool m1 = (f1 >= fs0 && f1 < fe0) || (f1 >= fs1 && f1 < fe1);
        const bool m2 = (f2 >= fs0 && f2 < fe0) || (f2 >= fs1 && f2 < fe1);
        const bool m3 = (f3 >= fs0 && f3 < fe0) || (f3 >= fs1 && f3 < fe1);
        float4 fmv;
        fmv.x = m0 ? 0.f : 1.f;
        fmv.y = m1 ? 0.f : 1.f;
        fmv.z = m2 ? 0.f : 1.f;
        fmv.w = m3 ? 0.f : 1.f;
        s_fm[q] = fmv;

        const unsigned fmz_ballot = __ballot_sync(0xFFFFFFFFu, m0 && m1 && m2 && m3);

        // per-row time-mask bitmap for this block's 32 rows
        const int tr = blockIdx.x * 32 + q;
        const bool tmask = (tr >= ts0 && tr < te0) || (tr >= ts1 && tr < te1);
        const unsigned t_ballot = __ballot_sync(0xFFFFFFFFu, tmask);

        if (q == 0) {
            s_fmz   = fmz_ballot;
            s_tbits = t_ballot;
        }
    }
    __syncthreads();

    // ---- cheap per-thread mask fetch ---------------------------------------
    const float4   fm    = s_fm[q];                       // one LDS.128
    const unsigned fmz   = (s_fmz >> q) & 1u;             // broadcast LDS
    const unsigned tbits = (s_tbits >> (w * 4)) & 0xFu;   // 4 row bits
    const unsigned skip  = fmz ? 0xFu : tbits;            // rows to skip

    // ---- streaming apply: 4 rows per thread (R5 body) ----------------------
    const int t0 = blockIdx.x * 32 + w * 4;
    const size_t base = ((size_t)b * T + t0) * 32 + q;

    bool p[4];
    #pragma unroll
    for (int i = 0; i < 4; i++) p[i] = ((skip >> i) & 1u) == 0u;

    float4 v[4];
    #pragma unroll
    for (int i = 0; i < 4; i++) {
        v[i] = make_float4(0.f, 0.f, 0.f, 0.f);
        if (p[i]) v[i] = __ldcs(x + base + (size_t)i * 32);
    }

    #pragma unroll
    for (int i = 0; i < 4; i++) {
        float4 r;
        if (p[i]) {
            r.x = v[i].x * fm.x;
            r.y = v[i].y * fm.y;
            r.z = v[i].z * fm.z;
            r.w = v[i].w * fm.w;
        } else {
            r = make_float4(0.f, 0.f, 0.f, 0.f);
        }
        __stcs(out + base + (size_t)i * 32, r);
    }
}

extern "C" void kernel_launch(void* const* d_in, const int* in_sizes, int n_in,
                              void* d_out, int out_size) {
    const float* x     = (const float*)d_in[0];
    const int*   x_len = (const int*)d_in[1];
    float*       out   = (float*)d_out;

    const int B = in_sizes[1];                 // 128
    const int F = 128;                         // fixed by problem shape
    const int T = in_sizes[0] / (B * F);       // 4000

    dim3 grid(T / 32, B);                      // 125 x 128 blocks, one node
    specaug_fused_kernel<<<grid, 256>>>(
        (const float4*)x, (float4*)out, x_len, T);
    (void)n_in; (void)out_size; (void)F;
}

// round 12
// speedup vs baseline: 1.0216x; 1.0035x over previous
#include <cuda_runtime.h>
#include <cstdint>

// ---------------------------------------------------------------------------
// SpecAugment on GB300 — FINAL (R11, best measured: 74.18us, rel_err 0.0).
//  * Single fused kernel, one graph node, memory-roofline-bound:
//    422 MB moved (analytic floor) at ~6.15 TB/s achieved.
//  * Subkeys of jax.random.split(key(42),3) constexpr-baked (threefry2x32,
//    JAX partitionable path) — bit-exact mask reproduction.
//  * Warp 0: 8 runtime hashes (SIMT lanes 0..7) -> intervals -> materialized
//    per-lane fm table (smem), row-mask bitmap, fmzero lane bitmap (ballot).
//  * Other warps: one LDS.128 + bit tests instead of ~28 ALU ops each.
//  * 256-thread block, 4 float4/thread, grid (T/32, B); streaming __ldcs/
//    __stcs; loads predicated off where the output is provably zero.
// B=128, T=4000, F=128.
// ---------------------------------------------------------------------------

#define FREQ_MASK_SIZE 27.0f
#define TIME_MASK_PCT  0.25f

// ---- constexpr Threefry2x32 (20 rounds) for compile-time subkeys ----------
struct TFPair { unsigned a, b; };

constexpr unsigned rotl32c(unsigned x, int r) {
    return (x << r) | (x >> (32 - r));
}

constexpr TFPair threefry_const(unsigned k0, unsigned k1,
                                unsigned x0, unsigned x1) {
    unsigned ks2 = k0 ^ k1 ^ 0x1BD11BDAu;
    x0 += k0; x1 += k1;
    const int R[8] = {13, 15, 26, 6, 17, 29, 16, 24};
    for (int g = 0; g < 5; g++) {
        const int* r = (g % 2 == 0) ? R : R + 4;
        for (int i = 0; i < 4; i++) {
            x0 += x1; x1 = rotl32c(x1, r[i]); x1 ^= x0;
        }
        switch (g) {
            case 0: x0 += k1;  x1 += ks2 + 1u; break;
            case 1: x0 += ks2; x1 += k0 + 2u;  break;
            case 2: x0 += k0;  x1 += k1 + 3u;  break;
            case 3: x0 += k1;  x1 += ks2 + 4u; break;
            case 4: x0 += ks2; x1 += k0 + 5u;  break;
        }
    }
    return TFPair{x0, x1};
}

// split(key(42), 3), partitionable path: child i = threefry(key, (0, i))
constexpr TFPair KF = threefry_const(0u, 42u, 0u, 0u);
constexpr TFPair KV = threefry_const(0u, 42u, 0u, 1u);
constexpr TFPair KS = threefry_const(0u, 42u, 0u, 2u);

// ---- device Threefry2x32 (same schedule) ----------------------------------
__device__ __forceinline__ uint2 threefry2x32(unsigned k0, unsigned k1,
                                              unsigned x0, unsigned x1) {
    unsigned ks2 = k0 ^ k1 ^ 0x1BD11BDAu;
    x0 += k0; x1 += k1;
#define TF_RND(r) { x0 += x1; x1 = __funnelshift_l(x1, x1, (r)); x1 ^= x0; }
    TF_RND(13) TF_RND(15) TF_RND(26) TF_RND(6)
    x0 += k1;  x1 += ks2 + 1u;
    TF_RND(17) TF_RND(29) TF_RND(16) TF_RND(24)
    x0 += ks2; x1 += k0 + 2u;
    TF_RND(13) TF_RND(15) TF_RND(26) TF_RND(6)
    x0 += k0;  x1 += k1 + 3u;
    TF_RND(17) TF_RND(29) TF_RND(16) TF_RND(24)
    x0 += k1;  x1 += ks2 + 4u;
    TF_RND(13) TF_RND(15) TF_RND(26) TF_RND(6)
    x0 += ks2; x1 += k0 + 5u;
#undef TF_RND
    return make_uint2(x0, x1);
}

__device__ __forceinline__ float bits_to_unit(unsigned bits) {
    return __uint_as_float((bits >> 9) | 0x3F800000u) - 1.0f;
}

// ---------------------------------------------------------------------------
// Fused kernel. Block = 256 threads = 8 warps; warp w handles t-rows
// [blockIdx.x*32 + w*4, +4) with 32 float4 lanes over F=128. Grid=(T/32, B).
// ---------------------------------------------------------------------------
__global__ void __launch_bounds__(256)
specaug_fused_kernel(const float4* __restrict__ x,
                     float4* __restrict__ out,
                     const int* __restrict__ x_len,
                     int T) {
    __shared__ int      s_iv[8];    // fs0,fe0,fs1,fe1, ts0,te0,ts1,te1
    __shared__ float4   s_fm[32];   // per-lane freq multiplier (bins 4q..4q+3)
    __shared__ unsigned s_tbits;    // bit r = time-mask for block row r (0..31)
    __shared__ unsigned s_fmz;      // bit q = all 4 bins of lane q masked

    const int b = blockIdx.y;
    const int w = threadIdx.x >> 5;
    const int q = threadIdx.x & 31;

    // ---- warp 0: hashes -> intervals -> materialized mask tables -----------
    if (w == 0) {
        const unsigned sel = (unsigned)q & 7u;
        unsigned k0, k1, j;
        if (sel < 4u)      { k0 = KF.a; k1 = KF.b; j = sel; }
        else if (sel < 6u) { k0 = KV.a; k1 = KV.b; j = 2u * (unsigned)b + (sel - 4u); }
        else               { k0 = KS.a; k1 = KS.b; j = 2u * (unsigned)b + (sel - 6u); }
        uint2 h = threefry2x32(k0, k1, 0u, j);
        float u = bits_to_unit(h.x ^ h.y);

        const unsigned FULL = 0xFFFFFFFFu;
        float u00 = __shfl_sync(FULL, u, 0);
        float u01 = __shfl_sync(FULL, u, 1);
        float u10 = __shfl_sync(FULL, u, 2);
        float u11 = __shfl_sync(FULL, u, 3);
        float uv0 = __shfl_sync(FULL, u, 4);
        float uv1 = __shfl_sync(FULL, u, 5);
        float us0 = __shfl_sync(FULL, u, 6);
        float us1 = __shfl_sync(FULL, u, 7);

        if (q == 0) {
            // frequency masks (fp32 ops matching the reference exactly);
            // floor results are exact small integers -> store as int.
            const float Ff = 128.0f;
            float fv0 = __fmul_rn(u00, FREQ_MASK_SIZE);
            float fb0 = __fmul_rn(u01, __fsub_rn(Ff, fv0));
            s_iv[0] = (int)floorf(fb0);
            s_iv[1] = (int)floorf(__fadd_rn(fb0, fv0));
            float fv1 = __fmul_rn(u10, FREQ_MASK_SIZE);
            float fb1 = __fmul_rn(u11, __fsub_rn(Ff, fv1));
            s_iv[2] = (int)floorf(fb1);
            s_iv[3] = (int)floorf(__fadd_rn(fb1, fv1));

            // adaptive time masks for batch b
            float xl = (float)__ldg(x_len + b);
            float tparam = floorf(__fmul_rn(TIME_MASK_PCT, xl));

            float tv0 = __fmul_rn(uv0, tparam);
            float tb0 = __fmul_rn(us0, __fsub_rn(xl, tv0));
            s_iv[4] = (int)floorf(tb0);
            s_iv[5] = (int)floorf(__fadd_rn(tb0, tv0));
            float tv1 = __fmul_rn(uv1, tparam);
            float tb1 = __fmul_rn(us1, __fsub_rn(xl, tv1));
            s_iv[6] = (int)floorf(tb1);
            s_iv[7] = (int)floorf(__fadd_rn(tb1, tv1));
        }
        __syncwarp();

        const int fs0 = s_iv[0], fe0 = s_iv[1], fs1 = s_iv[2], fe1 = s_iv[3];
        const int ts0 = s_iv[4], te0 = s_iv[5], ts1 = s_iv[6], te1 = s_iv[7];

        // per-lane freq multiplier table
        const int f0 = 4 * q;
        const int f1 = f0 + 1, f2 = f0 + 2, f3 = f0 + 3;
        const bool m0 = (f0 >= fs0 && f0 < fe0) || (f0 >= fs1 && f0 < fe1);
        const bool m1 = (f1 >= fs0 && f1 < fe0) || (f1 >= fs1 && f1 < fe1);
        const bool m2 = (f2 >= fs0 && f2 < fe0) || (f2 >= fs1 && f2 < fe1);
        const bool m3 = (f3 >= fs0 && f3 < fe0) || (f3 >= fs1 && f3 < fe1);
        float4 fmv;
        fmv.x = m0 ? 0.f : 1.f;
        fmv.y = m1 ? 0.f : 1.f;
        fmv.z = m2 ? 0.f : 1.f;
        fmv.w = m3 ? 0.f : 1.f;
        s_fm[q] = fmv;

        const unsigned fmz_ballot = __ballot_sync(0xFFFFFFFFu, m0 && m1 && m2 && m3);

        // per-row time-mask bitmap for this block's 32 rows
        const int tr = blockIdx.x * 32 + q;
        const bool tmask = (tr >= ts0 && tr < te0) || (tr >= ts1 && tr < te1);
        const unsigned t_ballot = __ballot_sync(0xFFFFFFFFu, tmask);

        if (q == 0) {
            s_fmz   = fmz_ballot;
            s_tbits = t_ballot;
        }
    }
    __syncthreads();

    // ---- cheap per-thread mask fetch ---------------------------------------
    const float4   fm    = s_fm[q];                       // one LDS.128
    const unsigned fmz   = (s_fmz >> q) & 1u;             // broadcast LDS
    const unsigned tbits = (s_tbits >> (w * 4)) & 0xFu;   // 4 row bits
    const unsigned skip  = fmz ? 0xFu : tbits;            // rows to skip

    // ---- streaming apply: 4 rows per thread --------------------------------
    const int t0 = blockIdx.x * 32 + w * 4;
    const size_t base = ((size_t)b * T + t0) * 32 + q;

    bool p[4];
    #pragma unroll
    for (int i = 0; i < 4; i++) p[i] = ((skip >> i) & 1u) == 0u;

    float4 v[4];
    #pragma unroll
    for (int i = 0; i < 4; i++) {
        v[i] = make_float4(0.f, 0.f, 0.f, 0.f);
        if (p[i]) v[i] = __ldcs(x + base + (size_t)i * 32);
    }

    #pragma unroll
    for (int i = 0; i < 4; i++) {
        float4 r;
        if (p[i]) {
            r.x = v[i].x * fm.x;
            r.y = v[i].y * fm.y;
            r.z = v[i].z * fm.z;
            r.w = v[i].w * fm.w;
        } else {
            r = make_float4(0.f, 0.f, 0.f, 0.f);
        }
        __stcs(out + base + (size_t)i * 32, r);
    }
}

extern "C" void kernel_launch(void* const* d_in, const int* in_sizes, int n_in,
                              void* d_out, int out_size) {
    const float* x     = (const float*)d_in[0];
    const int*   x_len = (const int*)d_in[1];
    float*       out   = (float*)d_out;

    const int B = in_sizes[1];                 // 128
    const int F = 128;                         // fixed by problem shape
    const int T = in_sizes[0] / (B * F);       // 4000

    dim3 grid(T / 32, B);                      // 125 x 128 blocks, one node
    specaug_fused_kernel<<<grid, 256>>>(
        (const float4*)x, (float4*)out, x_len, T);
    (void)n_in; (void)out_size; (void)F;
}